// round 2
// baseline (speedup 1.0000x reference)
#include <cuda_runtime.h>
#include <math.h>

// Problem dims (fixed for this dataset instance)
#define B_ 32
#define N_ 1024
#define C_ 64
#define D_ 512
#define K_ 20
#define RING 32
#define BIG_NEGF -1000000000.0f
#define LOG2PI 1.8378770664093453f

// Scratch (allocation-free rule: __device__ globals)
__device__ float d_emission[B_ * N_ * C_];   // 8 MB, stays L2-resident
__device__ float d_meansT[D_ * C_];          // means[c][d]/var[d], transposed [d][c]
__device__ float d_invvar[D_];
__device__ float d_m2[C_];
__device__ float d_const;                    // -0.5*(logdet + D*log(2pi))
__device__ float d_P[C_ * C_];               // exp(log_softmax(masked trans, axis=0))
__device__ float d_initlp[C_];
__device__ float d_lentab[K_ * C_];          // [duration-1][c]

// ---------------------------------------------------------------------------
// Prep: small parameter transforms (single CTA)
// ---------------------------------------------------------------------------
__global__ void __launch_bounds__(256) prep_kernel(
    const float* __restrict__ means, const float* __restrict__ cov,
    const float* __restrict__ tl, const float* __restrict__ il,
    const float* __restrict__ plr) {
  int tid = threadIdx.x;
  __shared__ float red[256];

  float lsum = 0.f;
  for (int d = tid; d < D_; d += 256) {
    float var = cov[d * D_ + d];
    float iv = 1.0f / var;
    d_invvar[d] = iv;
    lsum += logf(var);
    for (int cc = 0; cc < C_; ++cc) d_meansT[d * C_ + cc] = means[cc * D_ + d] * iv;
  }
  red[tid] = lsum;
  __syncthreads();
  for (int o = 128; o > 0; o >>= 1) {
    if (tid < o) red[tid] += red[tid + o];
    __syncthreads();
  }
  if (tid == 0) d_const = -0.5f * (red[0] + (float)D_ * LOG2PI);

  // m2[c] = sum_d means^2/var  (d_invvar visible after syncs above)
  for (int cc = tid; cc < C_; cc += 256) {
    float s = 0.f;
    for (int d = 0; d < D_; ++d) {
      float mm = means[cc * D_ + d];
      s += mm * mm * d_invvar[d];
    }
    d_m2[cc] = s;
  }

  // P[i][j] = softmax over i of masked transition logits (diag excluded)
  for (int j = tid; j < C_; j += 256) {
    float s = 0.f;
    for (int i = 0; i < C_; ++i)
      if (i != j) s += expf(tl[i * C_ + j]);
    float inv = 1.0f / s;
    for (int i = 0; i < C_; ++i)
      d_P[i * C_ + j] = (i == j) ? 0.f : expf(tl[i * C_ + j]) * inv;
  }

  // init log-softmax
  if (tid == 0) {
    float mx = -3e38f;
    for (int cc = 0; cc < C_; ++cc) mx = fmaxf(mx, il[cc]);
    float s = 0.f;
    for (int cc = 0; cc < C_; ++cc) s += expf(il[cc] - mx);
    float l = mx + logf(s);
    for (int cc = 0; cc < C_; ++cc) d_initlp[cc] = il[cc] - l;
  }

  // Poisson length log-probs: lentab[d][c], duration = d+1
  for (int idx = tid; idx < K_ * C_; idx += 256) {
    int d = idx / C_;
    int cc = idx % C_;
    float lr = plr[cc];
    d_lentab[idx] = (float)(d + 1) * lr - expf(lr) - lgammaf((float)(d + 2));
  }
}

// ---------------------------------------------------------------------------
// Emission GEMM: emission[bn][c] = cross - 0.5*x2 - 0.5*m2[c] + const
// Tile: 128 rows x 64 cols per CTA, D chunked by 32.
// ---------------------------------------------------------------------------
__global__ void __launch_bounds__(256) emission_kernel(const float* __restrict__ feat) {
  __shared__ float fs[128][33];
  __shared__ float4 ms4[32][17];
  __shared__ float ivs[32];

  int tid = threadIdx.x;
  int r0 = blockIdx.x * 128;
  int cg = tid & 15;   // cols cg*4 .. cg*4+3
  int rg = tid >> 4;   // rows rg*8 .. rg*8+7

  float acc[8][4];
  float xacc[8];
#pragma unroll
  for (int i = 0; i < 8; i++) {
    xacc[i] = 0.f;
#pragma unroll
    for (int j = 0; j < 4; j++) acc[i][j] = 0.f;
  }

  for (int k0 = 0; k0 < D_; k0 += 32) {
#pragma unroll
    for (int ii = 0; ii < 16; ii++) {
      int idx = tid + 256 * ii;
      int row = idx >> 5, col = idx & 31;
      fs[row][col] = feat[(r0 + row) * D_ + k0 + col];
    }
#pragma unroll
    for (int ii = 0; ii < 2; ii++) {
      int idx = tid + 256 * ii;
      int k = idx >> 4, c4 = idx & 15;
      ms4[k][c4] = ((const float4*)(d_meansT + (k0 + k) * C_))[c4];
    }
    if (tid < 32) ivs[tid] = d_invvar[k0 + tid];
    __syncthreads();

#pragma unroll
    for (int k = 0; k < 32; k++) {
      float4 bv = ms4[k][cg];
      float iv = ivs[k];
#pragma unroll
      for (int i = 0; i < 8; i++) {
        float a = fs[rg * 8 + i][k];
        acc[i][0] = fmaf(a, bv.x, acc[i][0]);
        acc[i][1] = fmaf(a, bv.y, acc[i][1]);
        acc[i][2] = fmaf(a, bv.z, acc[i][2]);
        acc[i][3] = fmaf(a, bv.w, acc[i][3]);
        xacc[i] = fmaf(a * a, iv, xacc[i]);
      }
    }
    __syncthreads();
  }

  float cst = d_const;
  float4 m2v = ((const float4*)d_m2)[cg];
#pragma unroll
  for (int i = 0; i < 8; i++) {
    int row = r0 + rg * 8 + i;
    float base = cst - 0.5f * xacc[i];
    float4 o;
    o.x = acc[i][0] - 0.5f * m2v.x + base;
    o.y = acc[i][1] - 0.5f * m2v.y + base;
    o.z = acc[i][2] - 0.5f * m2v.z + base;
    o.w = acc[i][3] - 0.5f * m2v.w + base;
    ((float4*)(d_emission + row * C_))[cg] = o;
  }
}

// ---------------------------------------------------------------------------
// Serial semi-Markov scan: one CTA per batch, 128 threads (2 threads / state).
//   g_s[c] = beta_s[c] - CE[s][c]   (ring of RING=32 slots, pad-65 rows)
//   alpha_t[c] = CE[t][c] + lse_{d=1..K}( g_{t-d}[c] + lenlp[d-1][c] )
//   beta_t[i]  = m + log( sum_j P[i,j] * exp(alpha[j]-m) )   (matvec, not lse!)
// ---------------------------------------------------------------------------
__global__ void __launch_bounds__(128) scan_kernel(const int* __restrict__ lengths,
                                                   float* __restrict__ out) {
  const int b = blockIdx.x;
  const int tid = threadIdx.x;
  const int lane = tid & 31;
  const int warp = tid >> 5;
  const int c = tid >> 1;   // state index 0..63
  const int h = tid & 1;    // half: h=0 -> d 1..10 / j 0..31 ; h=1 -> d 11..20 / j 32..63

  __shared__ float g_ring[RING * 65];
  __shared__ float e_s[130];    // two copies at offsets 0 and 65 (bank-disjoint)
  __shared__ float wmax[4];

  for (int i = tid; i < RING * 65; i += 128) g_ring[i] = BIG_NEGF;
  __syncthreads();
  if (tid < C_) g_ring[tid] = d_initlp[tid];   // slot 0 = s=0 (g_0 = init, CE[0]=0)

  float Preg[32];
#pragma unroll
  for (int jj = 0; jj < 32; jj++) Preg[jj] = d_P[c * C_ + h * 32 + jj];
  float lenr[10];
#pragma unroll
  for (int jj = 0; jj < 10; jj++) lenr[jj] = d_lentab[(h * 10 + jj) * C_ + c];

  const int len_b = lengths[b];
  const float* em = d_emission + b * N_ * C_;
  const int ebase = h ? 97 : 0;

  float CE_reg = 0.f;
  float emr = 0.f;
  if (h == 0) emr = em[c];   // row 0
  __syncthreads();

  for (int t = 1; t <= N_; ++t) {
    // running cumulative emission (even lanes own it; 1-row LDG prefetch)
    if (h == 0) {
      CE_reg += emr;
      if (t < N_) emr = em[t * C_ + c];
    }
    float CEc = __shfl_sync(0xffffffffu, CE_reg, lane & ~1);

    // alpha: lse over durations (10 per thread-half)
    float v[10];
    float mymax = -3.0e38f;
#pragma unroll
    for (int jj = 0; jj < 10; jj++) {
      int dd = h * 10 + jj + 1;
      int slot = (t - dd) & (RING - 1);
      v[jj] = g_ring[slot * 65 + c] + lenr[jj];
      mymax = fmaxf(mymax, v[jj]);
    }
    float pm = fmaxf(mymax, __shfl_xor_sync(0xffffffffu, mymax, 1));
    float sum = 0.f;
#pragma unroll
    for (int jj = 0; jj < 10; jj++) sum += __expf(v[jj] - pm);
    sum += __shfl_xor_sync(0xffffffffu, sum, 1);
    float alpha = CEc + pm + __logf(sum);

    // global max over alpha (warp tree + 4-way smem combine)
    float wm = alpha;
#pragma unroll
    for (int o = 16; o > 0; o >>= 1) wm = fmaxf(wm, __shfl_xor_sync(0xffffffffu, wm, o));
    if (lane == 0) wmax[warp] = wm;
    __syncthreads();
    float m = fmaxf(fmaxf(wmax[0], wmax[1]), fmaxf(wmax[2], wmax[3]));
    if (h == 0) {
      float ev = __expf(alpha - m);
      e_s[c] = ev;
      e_s[65 + c] = ev;
    }
    __syncthreads();

    // beta: plain matvec with exp(trans) in registers
    float acc = 0.f;
#pragma unroll
    for (int jj = 0; jj < 32; jj++) acc = fmaf(Preg[jj], e_s[ebase + jj], acc);
    acc += __shfl_xor_sync(0xffffffffu, acc, 1);
    if (h == 0) {
      float beta = m + __logf(fmaxf(acc, 1e-37f));
      g_ring[(t & (RING - 1)) * 65 + c] = beta - CE_reg;
    }

    if (t == len_b && tid == 0) {
      float se = 0.f;
      for (int j = 0; j < C_; j++) se += e_s[j];
      out[b] = m + __logf(se);
    }
    __syncthreads();
  }
}

// ---------------------------------------------------------------------------
extern "C" void kernel_launch(void* const* d_in, const int* in_sizes, int n_in,
                              void* d_out, int out_size) {
  const float* feat    = (const float*)d_in[0];
  const int*   lengths = (const int*)d_in[1];
  const float* means   = (const float*)d_in[2];
  const float* cov     = (const float*)d_in[3];
  const float* tl      = (const float*)d_in[4];
  const float* il      = (const float*)d_in[5];
  const float* plr     = (const float*)d_in[6];
  float* out = (float*)d_out;

  prep_kernel<<<1, 256>>>(means, cov, tl, il, plr);
  emission_kernel<<<(B_ * N_) / 128, 256>>>(feat);
  scan_kernel<<<B_, 128>>>(lengths, out);
}

// round 4
// speedup vs baseline: 1.8299x; 1.8299x over previous
#include <cuda_runtime.h>
#include <math.h>

// Problem dims (fixed for this dataset instance)
#define B_ 32
#define N_ 1024
#define C_ 64
#define D_ 512
#define K_ 20
#define LOG2PI 1.8378770664093453f
#define LOG2E 1.4426950408889634f
#define LN2F 0.6931471805599453f

// Scratch (allocation-free rule: __device__ globals)
__device__ float d_emission[B_ * N_ * C_];   // log2-domain emission, L2-resident (8MB)
__device__ float d_meansT[D_ * C_];          // means[c][d]/var[d], transposed [d][c]
__device__ float d_invvar[D_];
__device__ float d_m2[C_];
__device__ float d_const;                    // -0.5*(logdet + D*log(2pi))  (nat-log units)
__device__ float d_P[C_ * C_];               // exp(log_softmax(masked trans, axis=0))
__device__ float d_initlp[C_];               // log2 units
__device__ float d_lentab[K_ * C_];          // [duration-1][c], log2 units

__device__ __forceinline__ float ex2(float x) {
  float r; asm("ex2.approx.f32 %0, %1;" : "=f"(r) : "f"(x)); return r;
}
__device__ __forceinline__ float lg2(float x) {
  float r; asm("lg2.approx.f32 %0, %1;" : "=f"(r) : "f"(x)); return r;
}

// ---------------------------------------------------------------------------
// Small parameter transforms (single CTA, parallelized internally)
// ---------------------------------------------------------------------------
__global__ void __launch_bounds__(256) prep_kernel(
    const float* __restrict__ means, const float* __restrict__ cov,
    const float* __restrict__ tl, const float* __restrict__ il,
    const float* __restrict__ plr) {
  int tid = threadIdx.x;
  __shared__ float red[256];
  __shared__ float sme[64 * 65];
  __shared__ float invs[64];

  float lsum = 0.f;
  for (int d = tid; d < D_; d += 256) {
    float var = cov[d * D_ + d];
    d_invvar[d] = 1.0f / var;
    lsum += logf(var);
  }
  red[tid] = lsum;
  __syncthreads();
  for (int o = 128; o > 0; o >>= 1) {
    if (tid < o) red[tid] += red[tid + o];
    __syncthreads();
  }
  if (tid == 0) d_const = -0.5f * (red[0] + (float)D_ * LOG2PI);

  // m2[c] = sum_d means^2/var : warp per 8 states, lane-strided coalesced
  {
    int w = tid >> 5, ln = tid & 31;
    for (int i = 0; i < 8; i++) {
      int cc = w + 8 * i;
      float s = 0.f;
      for (int j = ln; j < D_; j += 32) {
        float mm = means[cc * D_ + j];
        s += mm * mm * d_invvar[j];
      }
      for (int o = 16; o > 0; o >>= 1) s += __shfl_xor_sync(0xffffffffu, s, o);
      if (ln == 0) d_m2[cc] = s;
    }
  }

  // P[i][j] = exp(tl[i][j]) / sum_{i'!=j} exp(tl[i'][j]), diag = 0
  for (int idx = tid; idx < 64 * 64; idx += 256) {
    int i = idx >> 6, j = idx & 63;
    sme[i * 65 + j] = (i == j) ? 0.f : expf(tl[i * 64 + j]);
  }
  __syncthreads();
  if (tid < 64) {
    float s = 0.f;
    for (int i = 0; i < 64; i++) s += sme[i * 65 + tid];
    invs[tid] = 1.0f / s;
  }
  __syncthreads();
  for (int idx = tid; idx < 64 * 64; idx += 256) {
    int i = idx >> 6, j = idx & 63;
    d_P[idx] = sme[i * 65 + j] * invs[j];
  }

  // init log-softmax (log2 units)
  if (tid == 0) {
    float mx = -3e38f;
    for (int cc = 0; cc < 64; cc++) mx = fmaxf(mx, il[cc]);
    float s = 0.f;
    for (int cc = 0; cc < 64; cc++) s += expf(il[cc] - mx);
    float l = mx + logf(s);
    for (int cc = 0; cc < 64; cc++) d_initlp[cc] = (il[cc] - l) * LOG2E;
  }

  // Poisson duration log-probs (log2 units)
  for (int idx = tid; idx < K_ * 64; idx += 256) {
    int dd = idx >> 6, cc = idx & 63;
    float lr = plr[cc];
    d_lentab[idx] = LOG2E * ((float)(dd + 1) * lr - expf(lr) - lgammaf((float)(dd + 2)));
  }
}

// ---------------------------------------------------------------------------
// Parallel transpose: meansT[d][c] = means[c][d] / var[d]
// ---------------------------------------------------------------------------
__global__ void __launch_bounds__(256) transpose_kernel(const float* __restrict__ means,
                                                        const float* __restrict__ cov) {
  __shared__ float tile[32][33];
  int d0 = blockIdx.x * 32, c0 = blockIdx.y * 32;
  int tx = threadIdx.x & 31, ty = threadIdx.x >> 5;
#pragma unroll
  for (int k = 0; k < 4; k++) {
    int cc = c0 + ty + 8 * k;
    tile[ty + 8 * k][tx] = means[cc * D_ + d0 + tx];
  }
  __syncthreads();
#pragma unroll
  for (int k = 0; k < 4; k++) {
    int dd = d0 + ty + 8 * k;
    float iv = 1.0f / cov[dd * D_ + dd];
    d_meansT[dd * C_ + c0 + tx] = tile[tx][ty + 8 * k] * iv;
  }
}

// ---------------------------------------------------------------------------
// Emission GEMM (outputs log2-domain): em2 = LOG2E*(cross - 0.5*x2 - 0.5*m2 + const)
// ---------------------------------------------------------------------------
__global__ void __launch_bounds__(256) emission_kernel(const float* __restrict__ feat) {
  __shared__ float fs[128][33];
  __shared__ float4 ms4[32][17];
  __shared__ float ivs[32];

  int tid = threadIdx.x;
  int r0 = blockIdx.x * 128;
  int cg = tid & 15;
  int rg = tid >> 4;

  float acc[8][4];
  float xacc[8];
#pragma unroll
  for (int i = 0; i < 8; i++) {
    xacc[i] = 0.f;
#pragma unroll
    for (int j = 0; j < 4; j++) acc[i][j] = 0.f;
  }

  for (int k0 = 0; k0 < D_; k0 += 32) {
#pragma unroll
    for (int ii = 0; ii < 16; ii++) {
      int idx = tid + 256 * ii;
      int row = idx >> 5, col = idx & 31;
      fs[row][col] = feat[(r0 + row) * D_ + k0 + col];
    }
#pragma unroll
    for (int ii = 0; ii < 2; ii++) {
      int idx = tid + 256 * ii;
      int k = idx >> 4, c4 = idx & 15;
      ms4[k][c4] = ((const float4*)(d_meansT + (k0 + k) * C_))[c4];
    }
    if (tid < 32) ivs[tid] = d_invvar[k0 + tid];
    __syncthreads();

#pragma unroll
    for (int k = 0; k < 32; k++) {
      float4 bv = ms4[k][cg];
      float iv = ivs[k];
#pragma unroll
      for (int i = 0; i < 8; i++) {
        float a = fs[rg * 8 + i][k];
        acc[i][0] = fmaf(a, bv.x, acc[i][0]);
        acc[i][1] = fmaf(a, bv.y, acc[i][1]);
        acc[i][2] = fmaf(a, bv.z, acc[i][2]);
        acc[i][3] = fmaf(a, bv.w, acc[i][3]);
        xacc[i] = fmaf(a * a, iv, xacc[i]);
      }
    }
    __syncthreads();
  }

  float cst = d_const;
  float4 m2v = ((const float4*)d_m2)[cg];
#pragma unroll
  for (int i = 0; i < 8; i++) {
    int row = r0 + rg * 8 + i;
    float base = cst - 0.5f * xacc[i];
    float4 o;
    o.x = LOG2E * (acc[i][0] - 0.5f * m2v.x + base);
    o.y = LOG2E * (acc[i][1] - 0.5f * m2v.y + base);
    o.z = LOG2E * (acc[i][2] - 0.5f * m2v.z + base);
    o.w = LOG2E * (acc[i][3] - 0.5f * m2v.w + base);
    ((float4*)(d_emission + row * C_))[cg] = o;
  }
}

// ---------------------------------------------------------------------------
// Semi-Markov scan v2: one CTA/batch, 128 threads, 2 threads/state.
// Register g-ring (20 deep, dup'd per pair), software-pipelined duration-LSE,
// 4-level shfl max (pair-duplicated values), 4-chain matvec, 2 bars/step, log2.
// ---------------------------------------------------------------------------
__global__ void __launch_bounds__(128, 1) scan_kernel(const int* __restrict__ lengths,
                                                      float* __restrict__ out) {
  const int b = blockIdx.x;
  const int tid = threadIdx.x;
  const int lane = tid & 31;
  const int warp = tid >> 5;
  const int c = tid >> 1;   // state 0..63
  const int h = tid & 1;    // half: h=0 handles partial d=2..10 / j 0..31, h=1 d=11..20 / j 32..63

  __shared__ __align__(16) float e_s[176];   // copy1 [0..63], copy2 [112..175] (bank-disjoint)
  __shared__ __align__(16) float wmax_s[4];

  float g[21];               // g[d] = beta_{t-d} - CE_{t-d}  (log2 units)
  g[1] = d_initlp[c];
#pragma unroll
  for (int d2 = 2; d2 <= 20; ++d2) g[d2] = -1.0e9f;

  float Preg[32];
#pragma unroll
  for (int jj = 0; jj < 32; jj++) Preg[jj] = d_P[c * 64 + (h ? 32 : 0) + jj];

  float lenr[10];
#pragma unroll
  for (int jj = 0; jj < 10; jj++)
    lenr[jj] = d_lentab[(h ? (jj + 10) : (jj + 1)) * 64 + c];
  if (!h) lenr[9] = -3.0e30f;   // dummy 10th term for uniform loop (never max, ex2->0)
  const float len0 = d_lentab[c];

  const int len_b = lengths[b];
  const float* em = d_emission + b * (N_ * C_);

  float CE = 0.f;
  float emr = em[c];                 // prefetch row 0
  float pm_p = -3.0e38f, sum_p = 0.f; // partial LSE over d>=2 for step t (empty at t=1)

  for (int t = 1; t <= N_; ++t) {
    CE += emr;
    if (t < N_) emr = em[t * 64 + c];

    // alpha_t = CE + lse( partial(d>=2), g[1]+len0 )
    float v1 = g[1] + len0;
    float M = fmaxf(pm_p, v1);
    float s = sum_p * ex2(pm_p - M) + ex2(v1 - M);
    float alpha = CE + M + lg2(s);

    // warp max: values duplicated across pairs -> xor1 level unnecessary (4 shfls)
    float wm = alpha;
    wm = fmaxf(wm, __shfl_xor_sync(0xffffffffu, wm, 16));
    wm = fmaxf(wm, __shfl_xor_sync(0xffffffffu, wm, 8));
    wm = fmaxf(wm, __shfl_xor_sync(0xffffffffu, wm, 4));
    wm = fmaxf(wm, __shfl_xor_sync(0xffffffffu, wm, 2));
    if (lane == 0) wmax_s[warp] = wm;

    // partial for t+1 (d=2..20 uses g_{t-1..t-19} = current g[1..19]) — off critical path
    float vv[10];
#pragma unroll
    for (int jj = 0; jj < 10; jj++) {
      float gv = h ? g[jj + 10] : g[jj + 1];
      vv[jj] = gv + lenr[jj];
    }
    float npm = vv[0];
#pragma unroll
    for (int jj = 1; jj < 10; jj++) npm = fmaxf(npm, vv[jj]);
    float nsum = 0.f;
#pragma unroll
    for (int jj = 0; jj < 10; jj++) nsum += ex2(vv[jj] - npm);

    __syncthreads();                       // BAR1: wmax visible
    float4 w4 = *(const float4*)wmax_s;
    float m = fmaxf(fmaxf(w4.x, w4.y), fmaxf(w4.z, w4.w));
    float e = ex2(alpha - m);
    e_s[(h ? 112 : 0) + c] = e;
    __syncthreads();                       // BAR2: e visible

    // beta_t[i] = m + log2( sum_j P[i,j] * e_j ), 4 accumulator chains
    const float4* Ep = (const float4*)(e_s + (h ? 144 : 0));
    float a0 = 0.f, a1 = 0.f, a2 = 0.f, a3 = 0.f;
#pragma unroll
    for (int q = 0; q < 8; q++) {
      float4 E = Ep[q];
      a0 = fmaf(Preg[4 * q + 0], E.x, a0);
      a1 = fmaf(Preg[4 * q + 1], E.y, a1);
      a2 = fmaf(Preg[4 * q + 2], E.z, a2);
      a3 = fmaf(Preg[4 * q + 3], E.w, a3);
    }
    float acc = (a0 + a1) + (a2 + a3);
    acc += __shfl_xor_sync(0xffffffffu, acc, 1);
    float beta = m + lg2(fmaxf(acc, 1e-30f));
    float g_t = beta - CE;

    if (t == len_b && tid == 0) {
      float se = 0.f;
      for (int j = 0; j < 64; j++) se += e_s[j];
      out[b] = (m + lg2(se)) * LN2F;
    }

    // shift register ring
#pragma unroll
    for (int d2 = 20; d2 >= 2; --d2) g[d2] = g[d2 - 1];
    g[1] = g_t;

    // merge partial across halves (both threads end with full d=2..20 partial)
    float om = __shfl_xor_sync(0xffffffffu, npm, 1);
    float os = __shfl_xor_sync(0xffffffffu, nsum, 1);
    float M2 = fmaxf(npm, om);
    sum_p = nsum * ex2(npm - M2) + os * ex2(om - M2);
    pm_p = M2;
  }
}

// ---------------------------------------------------------------------------
extern "C" void kernel_launch(void* const* d_in, const int* in_sizes, int n_in,
                              void* d_out, int out_size) {
  const float* feat    = (const float*)d_in[0];
  const int*   lengths = (const int*)d_in[1];
  const float* means   = (const float*)d_in[2];
  const float* cov     = (const float*)d_in[3];
  const float* tl      = (const float*)d_in[4];
  const float* il      = (const float*)d_in[5];
  const float* plr     = (const float*)d_in[6];
  float* out = (float*)d_out;

  prep_kernel<<<1, 256>>>(means, cov, tl, il, plr);
  transpose_kernel<<<dim3(16, 2), 256>>>(means, cov);
  emission_kernel<<<(B_ * N_) / 128, 256>>>(feat);
  scan_kernel<<<B_, 128>>>(lengths, out);
}

// round 5
// speedup vs baseline: 2.2300x; 1.2186x over previous
#include <cuda_runtime.h>
#include <math.h>

// Problem dims (fixed for this dataset instance)
#define B_ 32
#define N_ 1024
#define C_ 64
#define D_ 512
#define K_ 20
#define LOG2PI 1.8378770664093453f
#define LOG2E 1.4426950408889634f
#define LN2F 0.6931471805599453f

// Scratch (allocation-free rule: __device__ globals)
__device__ float d_emission[B_ * N_ * C_];   // log2-domain emission, L2-resident (8MB)
__device__ float d_meansT[D_ * C_];          // means[c][d]/var[d], transposed [d][c]
__device__ float d_invvar[D_];
__device__ float d_m2[C_];
__device__ float d_const;                    // -0.5*(logdet + D*log(2pi))  (nat-log units)
__device__ float d_P[C_ * C_];               // exp(log_softmax(masked trans, axis=0))
__device__ float d_initlp[C_];               // log2 units
__device__ float d_lentab[K_ * C_];          // [duration-1][c], log2 units

__device__ __forceinline__ float ex2(float x) {
  float r; asm("ex2.approx.f32 %0, %1;" : "=f"(r) : "f"(x)); return r;
}
__device__ __forceinline__ float lg2(float x) {
  float r; asm("lg2.approx.f32 %0, %1;" : "=f"(r) : "f"(x)); return r;
}

// ---------------------------------------------------------------------------
// Small parameter transforms (single CTA, parallelized internally)
// ---------------------------------------------------------------------------
__global__ void __launch_bounds__(256) prep_kernel(
    const float* __restrict__ means, const float* __restrict__ cov,
    const float* __restrict__ tl, const float* __restrict__ il,
    const float* __restrict__ plr) {
  int tid = threadIdx.x;
  __shared__ float red[256];
  __shared__ float sme[64 * 65];
  __shared__ float invs[64];

  float lsum = 0.f;
  for (int d = tid; d < D_; d += 256) {
    float var = cov[d * D_ + d];
    d_invvar[d] = 1.0f / var;
    lsum += logf(var);
  }
  red[tid] = lsum;
  __syncthreads();
  for (int o = 128; o > 0; o >>= 1) {
    if (tid < o) red[tid] += red[tid + o];
    __syncthreads();
  }
  if (tid == 0) d_const = -0.5f * (red[0] + (float)D_ * LOG2PI);

  // m2[c] = sum_d means^2/var : warp per 8 states, lane-strided coalesced
  {
    int w = tid >> 5, ln = tid & 31;
    for (int i = 0; i < 8; i++) {
      int cc = w + 8 * i;
      float s = 0.f;
      for (int j = ln; j < D_; j += 32) {
        float mm = means[cc * D_ + j];
        s += mm * mm * d_invvar[j];
      }
      for (int o = 16; o > 0; o >>= 1) s += __shfl_xor_sync(0xffffffffu, s, o);
      if (ln == 0) d_m2[cc] = s;
    }
  }

  // P[i][j] = exp(tl[i][j]) / sum_{i'!=j} exp(tl[i'][j]), diag = 0
  for (int idx = tid; idx < 64 * 64; idx += 256) {
    int i = idx >> 6, j = idx & 63;
    sme[i * 65 + j] = (i == j) ? 0.f : expf(tl[i * 64 + j]);
  }
  __syncthreads();
  if (tid < 64) {
    float s = 0.f;
    for (int i = 0; i < 64; i++) s += sme[i * 65 + tid];
    invs[tid] = 1.0f / s;
  }
  __syncthreads();
  for (int idx = tid; idx < 64 * 64; idx += 256) {
    int i = idx >> 6, j = idx & 63;
    d_P[idx] = sme[i * 65 + j] * invs[j];
  }

  // init log-softmax (log2 units)
  if (tid == 0) {
    float mx = -3e38f;
    for (int cc = 0; cc < 64; cc++) mx = fmaxf(mx, il[cc]);
    float s = 0.f;
    for (int cc = 0; cc < 64; cc++) s += expf(il[cc] - mx);
    float l = mx + logf(s);
    for (int cc = 0; cc < 64; cc++) d_initlp[cc] = (il[cc] - l) * LOG2E;
  }

  // Poisson duration log-probs (log2 units)
  for (int idx = tid; idx < K_ * 64; idx += 256) {
    int dd = idx >> 6, cc = idx & 63;
    float lr = plr[cc];
    d_lentab[idx] = LOG2E * ((float)(dd + 1) * lr - expf(lr) - lgammaf((float)(dd + 2)));
  }
}

// ---------------------------------------------------------------------------
// Parallel transpose: meansT[d][c] = means[c][d] / var[d]
// ---------------------------------------------------------------------------
__global__ void __launch_bounds__(256) transpose_kernel(const float* __restrict__ means,
                                                        const float* __restrict__ cov) {
  __shared__ float tile[32][33];
  int d0 = blockIdx.x * 32, c0 = blockIdx.y * 32;
  int tx = threadIdx.x & 31, ty = threadIdx.x >> 5;
#pragma unroll
  for (int k = 0; k < 4; k++) {
    int cc = c0 + ty + 8 * k;
    tile[ty + 8 * k][tx] = means[cc * D_ + d0 + tx];
  }
  __syncthreads();
#pragma unroll
  for (int k = 0; k < 4; k++) {
    int dd = d0 + ty + 8 * k;
    float iv = 1.0f / cov[dd * D_ + dd];
    d_meansT[dd * C_ + c0 + tx] = tile[tx][ty + 8 * k] * iv;
  }
}

// ---------------------------------------------------------------------------
// Emission GEMM (outputs log2-domain): em2 = LOG2E*(cross - 0.5*x2 - 0.5*m2 + const)
// ---------------------------------------------------------------------------
__global__ void __launch_bounds__(256) emission_kernel(const float* __restrict__ feat) {
  __shared__ float fs[128][33];
  __shared__ float4 ms4[32][17];
  __shared__ float ivs[32];

  int tid = threadIdx.x;
  int r0 = blockIdx.x * 128;
  int cg = tid & 15;
  int rg = tid >> 4;

  float acc[8][4];
  float xacc[8];
#pragma unroll
  for (int i = 0; i < 8; i++) {
    xacc[i] = 0.f;
#pragma unroll
    for (int j = 0; j < 4; j++) acc[i][j] = 0.f;
  }

  for (int k0 = 0; k0 < D_; k0 += 32) {
#pragma unroll
    for (int ii = 0; ii < 16; ii++) {
      int idx = tid + 256 * ii;
      int row = idx >> 5, col = idx & 31;
      fs[row][col] = feat[(r0 + row) * D_ + k0 + col];
    }
#pragma unroll
    for (int ii = 0; ii < 2; ii++) {
      int idx = tid + 256 * ii;
      int k = idx >> 4, c4 = idx & 15;
      ms4[k][c4] = ((const float4*)(d_meansT + (k0 + k) * C_))[c4];
    }
    if (tid < 32) ivs[tid] = d_invvar[k0 + tid];
    __syncthreads();

#pragma unroll
    for (int k = 0; k < 32; k++) {
      float4 bv = ms4[k][cg];
      float iv = ivs[k];
#pragma unroll
      for (int i = 0; i < 8; i++) {
        float a = fs[rg * 8 + i][k];
        acc[i][0] = fmaf(a, bv.x, acc[i][0]);
        acc[i][1] = fmaf(a, bv.y, acc[i][1]);
        acc[i][2] = fmaf(a, bv.z, acc[i][2]);
        acc[i][3] = fmaf(a, bv.w, acc[i][3]);
        xacc[i] = fmaf(a * a, iv, xacc[i]);
      }
    }
    __syncthreads();
  }

  float cst = d_const;
  float4 m2v = ((const float4*)d_m2)[cg];
#pragma unroll
  for (int i = 0; i < 8; i++) {
    int row = r0 + rg * 8 + i;
    float base = cst - 0.5f * xacc[i];
    float4 o;
    o.x = LOG2E * (acc[i][0] - 0.5f * m2v.x + base);
    o.y = LOG2E * (acc[i][1] - 0.5f * m2v.y + base);
    o.z = LOG2E * (acc[i][2] - 0.5f * m2v.z + base);
    o.w = LOG2E * (acc[i][3] - 0.5f * m2v.w + base);
    ((float4*)(d_emission + row * C_))[cg] = o;
  }
}

// ---------------------------------------------------------------------------
// Semi-Markov scan v3: one CTA/batch, 128 threads, 2 threads/state.
// NO max-reduction: predicted shift m (exact prev-max + drift correction),
// ONE bar/step, double-buffered e exchange, fused e = s * ex2(CE+M-m),
// emax piggybacked on matvec loads, 3-deep emission prefetch. Log2 domain.
// ---------------------------------------------------------------------------
__global__ void __launch_bounds__(128, 1) scan_kernel(const int* __restrict__ lengths,
                                                      float* __restrict__ out) {
  const int b = blockIdx.x;
  const int tid = threadIdx.x;
  const int c = tid >> 1;   // state 0..63
  const int h = tid & 1;    // half: h=0 -> durations 2..10 & j 0..31; h=1 -> 11..20 & j 32..63

  // double buffer: [parity][ copy1 0..63 | em0 slot 64 | copy2 112..175 ]
  __shared__ __align__(16) float e_s[2][192];

  float g[21];               // g[d] = beta_{t-d} - CE_{t-d}  (log2 units)
  g[1] = d_initlp[c];
#pragma unroll
  for (int d2 = 2; d2 <= 20; ++d2) g[d2] = -1.0e9f;

  float Preg[32];
#pragma unroll
  for (int jj = 0; jj < 32; jj++) Preg[jj] = d_P[c * 64 + (h ? 32 : 0) + jj];

  float lenr[10];
#pragma unroll
  for (int jj = 0; jj < 10; jj++)
    lenr[jj] = d_lentab[(h ? (jj + 10) : (jj + 1)) * 64 + c];
  if (!h) lenr[9] = -3.0e30f;   // dummy 10th term (never max, ex2->0)
  const float len0 = d_lentab[c];

  const int len_b = lengths[b];
  const float* em = d_emission + b * (N_ * C_);

  float CE = 0.f;
  float emr_a = em[c];          // row 0 (added at t=1)
  float emr_b = em[64 + c];     // row 1 (added at t=2)
  // shift estimate for step 1: alpha_1[state 0] exactly (same value in all threads)
  float m = em[0] + d_initlp[0] + d_lentab[0];

  float pm_p = -3.0e38f, sum_p = 0.f;  // pipelined partial LSE over d>=2 (empty at t=1)

  for (int t = 1; t <= N_; ++t) {
    const int buf = t & 1;
    // prefetch row t+1 (consumed at step t+2) — ~2 steps of latency cover
    float emr_c = 0.f;
    if (t + 1 < N_) emr_c = em[(t + 1) * 64 + c];

    CE += emr_a;

    // alpha_t = CE + lse(partial(d>=2), g[1]+len0);  e = ex2(alpha - m) fused:
    float v1 = g[1] + len0;
    float M = fmaxf(pm_p, v1);
    float s = sum_p * ex2(pm_p - M) + ex2(v1 - M);
    float e = s * ex2(CE + M - m);          // exact: s*2^(CE+M-m) = 2^(alpha-m)

    e_s[buf][(h ? 112 : 0) + c] = e;
    if (tid == 0) e_s[buf][64] = emr_b;     // emission row t, state 0 (drift corr.)

    // pipelined duration-partial for t+1 (uses g[1..19] before shift)
    float vv[10];
#pragma unroll
    for (int jj = 0; jj < 10; jj++) {
      float gv = h ? g[jj + 10] : g[jj + 1];
      vv[jj] = gv + lenr[jj];
    }
    float npm = vv[0];
#pragma unroll
    for (int jj = 1; jj < 10; jj++) npm = fmaxf(npm, vv[jj]);
    float nsum = 0.f;
#pragma unroll
    for (int jj = 0; jj < 10; jj++) nsum += ex2(vv[jj] - npm);
    // merge partial across the pair NOW (shfl latency hides in bar wait)
    {
      float om = __shfl_xor_sync(0xffffffffu, npm, 1);
      float os = __shfl_xor_sync(0xffffffffu, nsum, 1);
      float M2 = fmaxf(npm, om);
      sum_p = nsum * ex2(npm - M2) + os * ex2(om - M2);
      pm_p = M2;
    }

    __syncthreads();                        // single bar: e + em0 visible

    // beta_t[i] = m + log2( sum_j P[i,j]*e_j ); emax tracked on same loads
    const float4* Ep = (const float4*)(&e_s[buf][0] + (h ? 144 : 0));
    float a0 = 0.f, a1 = 0.f, a2 = 0.f, a3 = 0.f;
    float emx = 0.f;
#pragma unroll
    for (int q = 0; q < 8; q++) {
      float4 E = Ep[q];
      a0 = fmaf(Preg[4 * q + 0], E.x, a0);
      a1 = fmaf(Preg[4 * q + 1], E.y, a1);
      a2 = fmaf(Preg[4 * q + 2], E.z, a2);
      a3 = fmaf(Preg[4 * q + 3], E.w, a3);
      emx = fmaxf(emx, fmaxf(fmaxf(E.x, E.y), fmaxf(E.z, E.w)));
    }
    float acc = (a0 + a1) + (a2 + a3);
    acc += __shfl_xor_sync(0xffffffffu, acc, 1);
    emx = fmaxf(emx, __shfl_xor_sync(0xffffffffu, emx, 1));
    float em0n = e_s[buf][64];

    float g_t = (m - CE) + lg2(fmaxf(acc, 1e-30f));   // beta - CE

    if (t == len_b && tid == 0) {
      float se = 0.f;
      for (int j = 0; j < 64; j++) se += e_s[buf][j];
      out[b] = (m + lg2(se)) * LN2F;
    }

    // next shift: exact max alpha_t (= m + lg2 emax) + next emission at state 0
    m += lg2(emx) + em0n;

    // shift register ring
#pragma unroll
    for (int d2 = 20; d2 >= 2; --d2) g[d2] = g[d2 - 1];
    g[1] = g_t;

    emr_a = emr_b;
    emr_b = emr_c;
  }
}

// ---------------------------------------------------------------------------
extern "C" void kernel_launch(void* const* d_in, const int* in_sizes, int n_in,
                              void* d_out, int out_size) {
  const float* feat    = (const float*)d_in[0];
  const int*   lengths = (const int*)d_in[1];
  const float* means   = (const float*)d_in[2];
  const float* cov     = (const float*)d_in[3];
  const float* tl      = (const float*)d_in[4];
  const float* il      = (const float*)d_in[5];
  const float* plr     = (const float*)d_in[6];
  float* out = (float*)d_out;

  prep_kernel<<<1, 256>>>(means, cov, tl, il, plr);
  transpose_kernel<<<dim3(16, 2), 256>>>(means, cov);
  emission_kernel<<<(B_ * N_) / 128, 256>>>(feat);
  scan_kernel<<<B_, 128>>>(lengths, out);
}

// round 6
// speedup vs baseline: 2.3459x; 1.0520x over previous
#include <cuda_runtime.h>
#include <math.h>

// Problem dims (fixed for this dataset instance)
#define B_ 32
#define N_ 1024
#define C_ 64
#define D_ 512
#define K_ 20
#define LOG2PI 1.8378770664093453f
#define LOG2E 1.4426950408889634f
#define LN2F 0.6931471805599453f

// Scratch (allocation-free rule: __device__ globals)
__device__ float d_emission[B_ * N_ * C_];   // log2-domain emission, L2-resident (8MB)
__device__ float d_meansT[D_ * C_];          // means[c][d]/var[d], transposed [d][c]
__device__ float d_invvar[D_];
__device__ float d_m2[C_];
__device__ float d_const;                    // -0.5*(logdet + D*log(2pi))  (nat-log units)
__device__ float d_P[C_ * C_];               // exp(log_softmax(masked trans, axis=0))
__device__ float d_initlp[C_];               // log2 units
__device__ float d_lentab[K_ * C_];          // [duration-1][c], log2 units

__device__ __forceinline__ float ex2(float x) {
  float r; asm("ex2.approx.f32 %0, %1;" : "=f"(r) : "f"(x)); return r;
}
__device__ __forceinline__ float lg2(float x) {
  float r; asm("lg2.approx.f32 %0, %1;" : "=f"(r) : "f"(x)); return r;
}

// ---------------------------------------------------------------------------
// Small parameter transforms (single CTA, parallelized internally)
// ---------------------------------------------------------------------------
__global__ void __launch_bounds__(256) prep_kernel(
    const float* __restrict__ means, const float* __restrict__ cov,
    const float* __restrict__ tl, const float* __restrict__ il,
    const float* __restrict__ plr) {
  int tid = threadIdx.x;
  __shared__ float red[256];
  __shared__ float sme[64 * 65];
  __shared__ float invs[64];

  float lsum = 0.f;
  for (int d = tid; d < D_; d += 256) {
    float var = cov[d * D_ + d];
    d_invvar[d] = 1.0f / var;
    lsum += logf(var);
  }
  red[tid] = lsum;
  __syncthreads();
  for (int o = 128; o > 0; o >>= 1) {
    if (tid < o) red[tid] += red[tid + o];
    __syncthreads();
  }
  if (tid == 0) d_const = -0.5f * (red[0] + (float)D_ * LOG2PI);

  // m2[c] = sum_d means^2/var : warp per 8 states, lane-strided coalesced
  {
    int w = tid >> 5, ln = tid & 31;
    for (int i = 0; i < 8; i++) {
      int cc = w + 8 * i;
      float s = 0.f;
      for (int j = ln; j < D_; j += 32) {
        float mm = means[cc * D_ + j];
        s += mm * mm * d_invvar[j];
      }
      for (int o = 16; o > 0; o >>= 1) s += __shfl_xor_sync(0xffffffffu, s, o);
      if (ln == 0) d_m2[cc] = s;
    }
  }

  // P[i][j] = exp(tl[i][j]) / sum_{i'!=j} exp(tl[i'][j]), diag = 0
  for (int idx = tid; idx < 64 * 64; idx += 256) {
    int i = idx >> 6, j = idx & 63;
    sme[i * 65 + j] = (i == j) ? 0.f : expf(tl[i * 64 + j]);
  }
  __syncthreads();
  if (tid < 64) {
    float s = 0.f;
    for (int i = 0; i < 64; i++) s += sme[i * 65 + tid];
    invs[tid] = 1.0f / s;
  }
  __syncthreads();
  for (int idx = tid; idx < 64 * 64; idx += 256) {
    int i = idx >> 6, j = idx & 63;
    d_P[idx] = sme[i * 65 + j] * invs[j];
  }

  // init log-softmax (log2 units)
  if (tid == 0) {
    float mx = -3e38f;
    for (int cc = 0; cc < 64; cc++) mx = fmaxf(mx, il[cc]);
    float s = 0.f;
    for (int cc = 0; cc < 64; cc++) s += expf(il[cc] - mx);
    float l = mx + logf(s);
    for (int cc = 0; cc < 64; cc++) d_initlp[cc] = (il[cc] - l) * LOG2E;
  }

  // Poisson duration log-probs (log2 units)
  for (int idx = tid; idx < K_ * 64; idx += 256) {
    int dd = idx >> 6, cc = idx & 63;
    float lr = plr[cc];
    d_lentab[idx] = LOG2E * ((float)(dd + 1) * lr - expf(lr) - lgammaf((float)(dd + 2)));
  }
}

// ---------------------------------------------------------------------------
// Parallel transpose: meansT[d][c] = means[c][d] / var[d]
// ---------------------------------------------------------------------------
__global__ void __launch_bounds__(256) transpose_kernel(const float* __restrict__ means,
                                                        const float* __restrict__ cov) {
  __shared__ float tile[32][33];
  int d0 = blockIdx.x * 32, c0 = blockIdx.y * 32;
  int tx = threadIdx.x & 31, ty = threadIdx.x >> 5;
#pragma unroll
  for (int k = 0; k < 4; k++) {
    int cc = c0 + ty + 8 * k;
    tile[ty + 8 * k][tx] = means[cc * D_ + d0 + tx];
  }
  __syncthreads();
#pragma unroll
  for (int k = 0; k < 4; k++) {
    int dd = d0 + ty + 8 * k;
    float iv = 1.0f / cov[dd * D_ + dd];
    d_meansT[dd * C_ + c0 + tx] = tile[tx][ty + 8 * k] * iv;
  }
}

// ---------------------------------------------------------------------------
// Emission GEMM (outputs log2-domain): em2 = LOG2E*(cross - 0.5*x2 - 0.5*m2 + const)
// ---------------------------------------------------------------------------
__global__ void __launch_bounds__(256) emission_kernel(const float* __restrict__ feat) {
  __shared__ float fs[128][33];
  __shared__ float4 ms4[32][17];
  __shared__ float ivs[32];

  int tid = threadIdx.x;
  int r0 = blockIdx.x * 128;
  int cg = tid & 15;
  int rg = tid >> 4;

  float acc[8][4];
  float xacc[8];
#pragma unroll
  for (int i = 0; i < 8; i++) {
    xacc[i] = 0.f;
#pragma unroll
    for (int j = 0; j < 4; j++) acc[i][j] = 0.f;
  }

  for (int k0 = 0; k0 < D_; k0 += 32) {
#pragma unroll
    for (int ii = 0; ii < 16; ii++) {
      int idx = tid + 256 * ii;
      int row = idx >> 5, col = idx & 31;
      fs[row][col] = feat[(r0 + row) * D_ + k0 + col];
    }
#pragma unroll
    for (int ii = 0; ii < 2; ii++) {
      int idx = tid + 256 * ii;
      int k = idx >> 4, c4 = idx & 15;
      ms4[k][c4] = ((const float4*)(d_meansT + (k0 + k) * C_))[c4];
    }
    if (tid < 32) ivs[tid] = d_invvar[k0 + tid];
    __syncthreads();

#pragma unroll
    for (int k = 0; k < 32; k++) {
      float4 bv = ms4[k][cg];
      float iv = ivs[k];
#pragma unroll
      for (int i = 0; i < 8; i++) {
        float a = fs[rg * 8 + i][k];
        acc[i][0] = fmaf(a, bv.x, acc[i][0]);
        acc[i][1] = fmaf(a, bv.y, acc[i][1]);
        acc[i][2] = fmaf(a, bv.z, acc[i][2]);
        acc[i][3] = fmaf(a, bv.w, acc[i][3]);
        xacc[i] = fmaf(a * a, iv, xacc[i]);
      }
    }
    __syncthreads();
  }

  float cst = d_const;
  float4 m2v = ((const float4*)d_m2)[cg];
#pragma unroll
  for (int i = 0; i < 8; i++) {
    int row = r0 + rg * 8 + i;
    float base = cst - 0.5f * xacc[i];
    float4 o;
    o.x = LOG2E * (acc[i][0] - 0.5f * m2v.x + base);
    o.y = LOG2E * (acc[i][1] - 0.5f * m2v.y + base);
    o.z = LOG2E * (acc[i][2] - 0.5f * m2v.z + base);
    o.w = LOG2E * (acc[i][3] - 0.5f * m2v.w + base);
    ((float4*)(d_emission + row * C_))[cg] = o;
  }
}

// ---------------------------------------------------------------------------
// Semi-Markov scan v4: one CTA/batch, 128 threads, 2 threads/state.
// - M := pm_p  -> SF/L0 precomputable, short g_t -> e chain (FADD,ex2,FADD,FMUL)
// - shift m via delay-2 beta0 smem relay (no emax tracking, no reductions)
// - unroll x4 with static register-ring rotation; 3-deep emission prefetch
// - one bar/step, double-buffered e exchange, log2 domain
// ---------------------------------------------------------------------------
__global__ void __launch_bounds__(128, 1) scan_kernel(const int* __restrict__ lengths,
                                                      float* __restrict__ out) {
  const int b = blockIdx.x;
  const int tid = threadIdx.x;
  const int c = tid >> 1;   // state 0..63
  const int h = tid & 1;    // h=0: durations 2..10, j 0..31 ; h=1: 11..20, j 32..63

  // double buffer: [parity][ copy1 0..63 | em0 slot 64 | copy2 112..175 ]
  __shared__ __align__(16) float e_s[2][192];
  __shared__ float sbeta_s[2];

  // register ring: at group start (t = 4k+1), g_d = G[d+3], d=1..20
  float G[24];
#pragma unroll
  for (int i = 0; i < 24; i++) G[i] = -1.0e9f;
  G[4] = d_initlp[c];

  float Preg[32];
#pragma unroll
  for (int jj = 0; jj < 32; jj++) Preg[jj] = d_P[c * 64 + (h ? 32 : 0) + jj];

  float lenr[10];
#pragma unroll
  for (int jj = 0; jj < 10; jj++)
    lenr[jj] = d_lentab[(h ? (jj + 10) : (jj + 1)) * 64 + c];
  if (!h) lenr[9] = -3.0e30f;   // dummy term (ex2 -> 0, never the max)
  const float len0 = d_lentab[c];

  const int len_b = lengths[b];
  const float* em = d_emission + b * (N_ * C_);

  float CE = 0.f;
  float emr0 = em[c];            // row 0 (consumed at t=1)
  float emr1 = em[64 + c];       // row 1
  float emr2 = em[128 + c];      // row 2
  float em0_prev = em[0];        // emission row0, state 0 (broadcast)
  float m = em[0] + d_initlp[0] + d_lentab[0];   // exact alpha_1[0]

  if (tid == 0) sbeta_s[0] = d_initlp[0];        // "beta_0[0]"
  float pm_p = 0.f, sum_p = 0.f;                 // partial LSE (empty at t=1)

  __syncthreads();

#define STEP(P)                                                                 \
  {                                                                             \
    const int t = tb + (P) + 1;                                                 \
    const int BUF = ((P) + 1) & 1;                                              \
    CE += emr0;                                                                 \
    float SF = ex2(CE + pm_p - m);                                              \
    float L0 = len0 - pm_p;                                                     \
    float mc = m - CE;                                                          \
    float emNew = 0.f;                                                          \
    if (t + 2 < N_) emNew = em[(t + 2) * 64 + c];                               \
    /* e_t = 2^(alpha_t - m), exact: (sum_p + 2^(v1-pm_p)) * 2^(CE+pm_p-m) */   \
    float e = (sum_p + ex2(G[4 - (P)] + L0)) * SF;                              \
    e_s[BUF][(h ? 112 : 0) + c] = e;                                            \
    if (tid == 0) e_s[BUF][64] = emr1;                                          \
    /* pipelined duration partial for t+1 (d=2..20 over g_1..g_19) */           \
    {                                                                           \
      float vv[10];                                                             \
      _Pragma("unroll")                                                         \
      for (int jj = 0; jj < 10; jj++) {                                         \
        float gv = h ? G[jj + 13 - (P)] : G[jj + 4 - (P)];                      \
        vv[jj] = gv + lenr[jj];                                                 \
      }                                                                         \
      float npm = vv[0];                                                        \
      _Pragma("unroll")                                                         \
      for (int jj = 1; jj < 10; jj++) npm = fmaxf(npm, vv[jj]);                 \
      float nsum = 0.f;                                                         \
      _Pragma("unroll")                                                         \
      for (int jj = 0; jj < 10; jj++) nsum += ex2(vv[jj] - npm);                \
      float om = __shfl_xor_sync(0xffffffffu, npm, 1);                          \
      float os = __shfl_xor_sync(0xffffffffu, nsum, 1);                         \
      float M2 = fmaxf(npm, om);                                                \
      sum_p = nsum * ex2(npm - M2) + os * ex2(om - M2);                         \
      pm_p = M2;                                                                \
    }                                                                           \
    __syncthreads();                                                            \
    const float4* Ep = (const float4*)(&e_s[BUF][0] + (h ? 144 : 0));           \
    float a0 = 0.f, a1 = 0.f, a2 = 0.f, a3 = 0.f;                               \
    _Pragma("unroll")                                                           \
    for (int q = 0; q < 8; q++) {                                               \
      float4 E = Ep[q];                                                         \
      a0 = fmaf(Preg[4 * q + 0], E.x, a0);                                      \
      a1 = fmaf(Preg[4 * q + 1], E.y, a1);                                      \
      a2 = fmaf(Preg[4 * q + 2], E.z, a2);                                      \
      a3 = fmaf(Preg[4 * q + 3], E.w, a3);                                      \
    }                                                                           \
    float acc = (a0 + a1) + (a2 + a3);                                          \
    acc += __shfl_xor_sync(0xffffffffu, acc, 1);                                \
    float em0n = e_s[BUF][64];                                                  \
    float sb = sbeta_s[(P) & 1];                                                \
    float gt = mc + lg2(fmaxf(acc, 1e-30f));                                    \
    G[3 - (P)] = gt;                                                            \
    if (tid == 0) sbeta_s[((P) + 1) & 1] = gt + CE;                             \
    if (t == len_b && tid == 0) {                                               \
      float se = 0.f;                                                           \
      for (int j = 0; j < 64; j++) se += e_s[BUF][j];                           \
      out[b] = (m + lg2(se)) * LN2F;                                            \
    }                                                                           \
    m = sb + em0_prev + em0n;                                                   \
    em0_prev = em0n;                                                            \
    emr0 = emr1; emr1 = emr2; emr2 = emNew;                                     \
  }

  for (int tb = 0; tb < N_; tb += 4) {
    STEP(0)
    STEP(1)
    STEP(2)
    STEP(3)
    // restore group invariant: shift ring by 4
#pragma unroll
    for (int i = 23; i >= 4; i--) G[i] = G[i - 4];
  }
#undef STEP
}

// ---------------------------------------------------------------------------
extern "C" void kernel_launch(void* const* d_in, const int* in_sizes, int n_in,
                              void* d_out, int out_size) {
  const float* feat    = (const float*)d_in[0];
  const int*   lengths = (const int*)d_in[1];
  const float* means   = (const float*)d_in[2];
  const float* cov     = (const float*)d_in[3];
  const float* tl      = (const float*)d_in[4];
  const float* il      = (const float*)d_in[5];
  const float* plr     = (const float*)d_in[6];
  float* out = (float*)d_out;

  prep_kernel<<<1, 256>>>(means, cov, tl, il, plr);
  transpose_kernel<<<dim3(16, 2), 256>>>(means, cov);
  emission_kernel<<<(B_ * N_) / 128, 256>>>(feat);
  scan_kernel<<<B_, 128>>>(lengths, out);
}

// round 7
// speedup vs baseline: 2.9070x; 1.2392x over previous
#include <cuda_runtime.h>
#include <cuda_bf16.h>
#include <math.h>

// Problem dims (fixed for this dataset instance)
#define B_ 32
#define N_ 1024
#define C_ 64
#define D_ 512
#define K_ 20
#define LOG2PI 1.8378770664093453f
#define LOG2E 1.4426950408889634f
#define LN2F 0.6931471805599453f

// Scratch (allocation-free rule: __device__ globals)
__device__ float d_emission[B_ * N_ * C_];   // log2-domain emission, L2-resident (8MB)
__device__ float d_meansT[D_ * C_];          // means[c][d]/var[d], transposed [d][c]
__device__ float d_invvar[D_];
__device__ float d_m2[C_];
__device__ float d_const;                    // -0.5*(logdet + D*log(2pi))  (nat-log units)
__device__ float d_P[C_ * C_];               // exp(log_softmax(masked trans, axis=0))
__device__ float d_initlp[C_];               // log2 units
__device__ float d_lentab[K_ * C_];          // [duration-1][c], log2 units

__device__ __forceinline__ float ex2(float x) {
  float r; asm("ex2.approx.f32 %0, %1;" : "=f"(r) : "f"(x)); return r;
}
__device__ __forceinline__ float lg2(float x) {
  float r; asm("lg2.approx.f32 %0, %1;" : "=f"(r) : "f"(x)); return r;
}

// ---------------------------------------------------------------------------
// Small parameter transforms (single CTA, parallelized internally)
// ---------------------------------------------------------------------------
__global__ void __launch_bounds__(256) prep_kernel(
    const float* __restrict__ means, const float* __restrict__ cov,
    const float* __restrict__ tl, const float* __restrict__ il,
    const float* __restrict__ plr) {
  int tid = threadIdx.x;
  __shared__ float red[256];
  __shared__ float sme[64 * 65];
  __shared__ float invs[64];

  float lsum = 0.f;
  for (int d = tid; d < D_; d += 256) {
    float var = cov[d * D_ + d];
    d_invvar[d] = 1.0f / var;
    lsum += logf(var);
  }
  red[tid] = lsum;
  __syncthreads();
  for (int o = 128; o > 0; o >>= 1) {
    if (tid < o) red[tid] += red[tid + o];
    __syncthreads();
  }
  if (tid == 0) d_const = -0.5f * (red[0] + (float)D_ * LOG2PI);

  // m2[c] = sum_d means^2/var : warp per 8 states, lane-strided coalesced
  {
    int w = tid >> 5, ln = tid & 31;
    for (int i = 0; i < 8; i++) {
      int cc = w + 8 * i;
      float s = 0.f;
      for (int j = ln; j < D_; j += 32) {
        float mm = means[cc * D_ + j];
        s += mm * mm * d_invvar[j];
      }
      for (int o = 16; o > 0; o >>= 1) s += __shfl_xor_sync(0xffffffffu, s, o);
      if (ln == 0) d_m2[cc] = s;
    }
  }

  // P[i][j] = exp(tl[i][j]) / sum_{i'!=j} exp(tl[i'][j]), diag = 0
  for (int idx = tid; idx < 64 * 64; idx += 256) {
    int i = idx >> 6, j = idx & 63;
    sme[i * 65 + j] = (i == j) ? 0.f : expf(tl[i * 64 + j]);
  }
  __syncthreads();
  if (tid < 64) {
    float s = 0.f;
    for (int i = 0; i < 64; i++) s += sme[i * 65 + tid];
    invs[tid] = 1.0f / s;
  }
  __syncthreads();
  for (int idx = tid; idx < 64 * 64; idx += 256) {
    int i = idx >> 6, j = idx & 63;
    d_P[idx] = sme[i * 65 + j] * invs[j];
  }

  // init log-softmax (log2 units)
  if (tid == 0) {
    float mx = -3e38f;
    for (int cc = 0; cc < 64; cc++) mx = fmaxf(mx, il[cc]);
    float s = 0.f;
    for (int cc = 0; cc < 64; cc++) s += expf(il[cc] - mx);
    float l = mx + logf(s);
    for (int cc = 0; cc < 64; cc++) d_initlp[cc] = (il[cc] - l) * LOG2E;
  }

  // Poisson duration log-probs (log2 units)
  for (int idx = tid; idx < K_ * 64; idx += 256) {
    int dd = idx >> 6, cc = idx & 63;
    float lr = plr[cc];
    d_lentab[idx] = LOG2E * ((float)(dd + 1) * lr - expf(lr) - lgammaf((float)(dd + 2)));
  }
}

// ---------------------------------------------------------------------------
// Parallel transpose: meansT[d][c] = means[c][d] / var[d]
// ---------------------------------------------------------------------------
__global__ void __launch_bounds__(256) transpose_kernel(const float* __restrict__ means,
                                                        const float* __restrict__ cov) {
  __shared__ float tile[32][33];
  int d0 = blockIdx.x * 32, c0 = blockIdx.y * 32;
  int tx = threadIdx.x & 31, ty = threadIdx.x >> 5;
#pragma unroll
  for (int k = 0; k < 4; k++) {
    int cc = c0 + ty + 8 * k;
    tile[ty + 8 * k][tx] = means[cc * D_ + d0 + tx];
  }
  __syncthreads();
#pragma unroll
  for (int k = 0; k < 4; k++) {
    int dd = d0 + ty + 8 * k;
    float iv = 1.0f / cov[dd * D_ + dd];
    d_meansT[dd * C_ + c0 + tx] = tile[tx][ty + 8 * k] * iv;
  }
}

// ---------------------------------------------------------------------------
// Emission GEMM (outputs log2-domain): em2 = LOG2E*(cross - 0.5*x2 - 0.5*m2 + const)
// ---------------------------------------------------------------------------
__global__ void __launch_bounds__(256) emission_kernel(const float* __restrict__ feat) {
  __shared__ float fs[128][33];
  __shared__ float4 ms4[32][17];
  __shared__ float ivs[32];

  int tid = threadIdx.x;
  int r0 = blockIdx.x * 128;
  int cg = tid & 15;
  int rg = tid >> 4;

  float acc[8][4];
  float xacc[8];
#pragma unroll
  for (int i = 0; i < 8; i++) {
    xacc[i] = 0.f;
#pragma unroll
    for (int j = 0; j < 4; j++) acc[i][j] = 0.f;
  }

  for (int k0 = 0; k0 < D_; k0 += 32) {
#pragma unroll
    for (int ii = 0; ii < 16; ii++) {
      int idx = tid + 256 * ii;
      int row = idx >> 5, col = idx & 31;
      fs[row][col] = feat[(r0 + row) * D_ + k0 + col];
    }
#pragma unroll
    for (int ii = 0; ii < 2; ii++) {
      int idx = tid + 256 * ii;
      int k = idx >> 4, c4 = idx & 15;
      ms4[k][c4] = ((const float4*)(d_meansT + (k0 + k) * C_))[c4];
    }
    if (tid < 32) ivs[tid] = d_invvar[k0 + tid];
    __syncthreads();

#pragma unroll
    for (int k = 0; k < 32; k++) {
      float4 bv = ms4[k][cg];
      float iv = ivs[k];
#pragma unroll
      for (int i = 0; i < 8; i++) {
        float a = fs[rg * 8 + i][k];
        acc[i][0] = fmaf(a, bv.x, acc[i][0]);
        acc[i][1] = fmaf(a, bv.y, acc[i][1]);
        acc[i][2] = fmaf(a, bv.z, acc[i][2]);
        acc[i][3] = fmaf(a, bv.w, acc[i][3]);
        xacc[i] = fmaf(a * a, iv, xacc[i]);
      }
    }
    __syncthreads();
  }

  float cst = d_const;
  float4 m2v = ((const float4*)d_m2)[cg];
#pragma unroll
  for (int i = 0; i < 8; i++) {
    int row = r0 + rg * 8 + i;
    float base = cst - 0.5f * xacc[i];
    float4 o;
    o.x = LOG2E * (acc[i][0] - 0.5f * m2v.x + base);
    o.y = LOG2E * (acc[i][1] - 0.5f * m2v.y + base);
    o.z = LOG2E * (acc[i][2] - 0.5f * m2v.z + base);
    o.w = LOG2E * (acc[i][3] - 0.5f * m2v.w + base);
    ((float4*)(d_emission + row * C_))[cg] = o;
  }
}

// ---------------------------------------------------------------------------
// Semi-Markov scan v5: LINEAR-DOMAIN duration ring.
// W_s = 2^(g_s - rho_t), rho_t = m_{t-1} - CE_{t-1}[c]  ==>  new entry W_t = acc_t
// exactly, duration-LSE becomes an FMA dot with precomputed L = 2^len,
// one ex2/step (sc) serves both ring rescale and e-scale. bf16 HFMA2 matvec.
// One bar/step, 2 threads/state (h splits durations 1..10 / 11..20 and j halves).
// ---------------------------------------------------------------------------
__global__ void __launch_bounds__(128, 1) scan_kernel(const int* __restrict__ lengths,
                                                      float* __restrict__ out) {
  const int b = blockIdx.x;
  const int tid = threadIdx.x;
  const int c = tid >> 1;   // state 0..63
  const int h = tid & 1;    // h=0: durations 1..10, j 0..31 ; h=1: 11..20, j 32..63

  __shared__ __align__(16) __nv_bfloat16 e_b[2][64];  // double-buffered e (bf16)
  __shared__ float em0_s[2];
  __shared__ float sbeta_s[2];

  // linear ring: h=0 W[i] = W_{t-1-i}, h=1 W[i] = W_{t-11-i}
  float W[10];
#pragma unroll
  for (int i = 0; i < 10; i++) W[i] = 0.f;
  if (h == 0) W[0] = ex2(d_initlp[c]);

  // linear duration weights L[i] = 2^{len}(dur = h*10 + i + 1)
  float L[10];
#pragma unroll
  for (int i = 0; i < 10; i++) L[i] = ex2(d_lentab[(h * 10 + i) * 64 + c]);

  // transition row (bf16x2 pairs over this thread's j-half)
  __nv_bfloat162 P2[16];
#pragma unroll
  for (int q = 0; q < 16; q++) {
    float p0 = d_P[c * 64 + h * 32 + 2 * q];
    float p1 = d_P[c * 64 + h * 32 + 2 * q + 1];
    P2[q] = __floats2bfloat162_rn(p0, p1);
  }

  const int len_b = lengths[b];
  const float* em = d_emission + b * (N_ * C_);
  float emr0 = em[c];          // row t-1 (0-idx) = em_t[c]
  float emr1 = em[64 + c];
  float emr2 = em[128 + c];
  float em0_prev = em[0];
  float m = em[0] + d_initlp[0] + d_lentab[0];   // exact alpha_1[0] (log2)
  float m_prev = 0.f;

  if (tid == 0) sbeta_s[0] = d_initlp[0];
  __syncthreads();

#define STEP(P)                                                                 \
  {                                                                             \
    const int t = tb + (P) + 1;                                                 \
    const int BUF = ((P) + 1) & 1;                                              \
    float emNew = 0.f;                                                          \
    if (t + 2 < N_) emNew = em[(t + 2) * 64 + c];                               \
    float dm = m - m_prev;                                                      \
    float sc = ex2(emr0 - dm);   /* = 2^(em_t[c] + m_{t-1} - m_t) */            \
    /* duration dot (linear): two 5-deep chains */                              \
    float s0 = W[0] * L[0];                                                     \
    float s1 = W[1] * L[1];                                                     \
    _Pragma("unroll")                                                           \
    for (int i = 2; i < 10; i += 2) {                                           \
      s0 = fmaf(W[i], L[i], s0);                                                \
      s1 = fmaf(W[i + 1], L[i + 1], s1);                                        \
    }                                                                           \
    float S = s0 + s1;                                                          \
    S += __shfl_xor_sync(0xffffffffu, S, 1);                                    \
    float e = S * sc;            /* = 2^(alpha_t - m_t) */                      \
    e_b[BUF][c] = __float2bfloat16(e);                                          \
    if (tid == 0) em0_s[BUF] = emr1;                                            \
    /* rescale ring to rho_{t+1}, pass aging entry to h=1, shift */             \
    _Pragma("unroll")                                                           \
    for (int i = 0; i < 10; i++) W[i] *= sc;                                    \
    float pass = __shfl_xor_sync(0xffffffffu, W[9], 1);                         \
    _Pragma("unroll")                                                           \
    for (int i = 9; i >= 1; i--) W[i] = W[i - 1];                               \
    __syncthreads();                                                            \
    /* matvec over e (bf16): broadcast 16B loads, 16 HFMA2 in 4 chains */       \
    const uint4* Ev = (const uint4*)(&e_b[BUF][h * 32]);                        \
    uint4 u0 = Ev[0], u1 = Ev[1], u2 = Ev[2], u3 = Ev[3];                       \
    const __nv_bfloat162* ep0 = (const __nv_bfloat162*)&u0;                     \
    const __nv_bfloat162* ep1 = (const __nv_bfloat162*)&u1;                     \
    const __nv_bfloat162* ep2 = (const __nv_bfloat162*)&u2;                     \
    const __nv_bfloat162* ep3 = (const __nv_bfloat162*)&u3;                     \
    __nv_bfloat162 a0 = __hmul2(P2[0], ep0[0]);                                 \
    __nv_bfloat162 a1 = __hmul2(P2[1], ep0[1]);                                 \
    __nv_bfloat162 a2 = __hmul2(P2[2], ep0[2]);                                 \
    __nv_bfloat162 a3 = __hmul2(P2[3], ep0[3]);                                 \
    a0 = __hfma2(P2[4], ep1[0], a0);                                            \
    a1 = __hfma2(P2[5], ep1[1], a1);                                            \
    a2 = __hfma2(P2[6], ep1[2], a2);                                            \
    a3 = __hfma2(P2[7], ep1[3], a3);                                            \
    a0 = __hfma2(P2[8], ep2[0], a0);                                            \
    a1 = __hfma2(P2[9], ep2[1], a1);                                            \
    a2 = __hfma2(P2[10], ep2[2], a2);                                           \
    a3 = __hfma2(P2[11], ep2[3], a3);                                           \
    a0 = __hfma2(P2[12], ep3[0], a0);                                           \
    a1 = __hfma2(P2[13], ep3[1], a1);                                           \
    a2 = __hfma2(P2[14], ep3[2], a2);                                           \
    a3 = __hfma2(P2[15], ep3[3], a3);                                           \
    float2 f0 = __bfloat1622float2(a0);                                         \
    float2 f1 = __bfloat1622float2(a1);                                         \
    float2 f2 = __bfloat1622float2(a2);                                         \
    float2 f3 = __bfloat1622float2(a3);                                         \
    float acc = ((f0.x + f0.y) + (f1.x + f1.y)) + ((f2.x + f2.y) + (f3.x + f3.y)); \
    acc += __shfl_xor_sync(0xffffffffu, acc, 1);                                \
    float em0n = em0_s[BUF];                                                    \
    float sb = sbeta_s[(P) & 1];                                                \
    W[0] = h ? pass : acc;       /* new ring entry W_t = acc_t (exact) */       \
    if (tid == 0) sbeta_s[((P) + 1) & 1] = m + lg2(fmaxf(acc, 1e-30f));         \
    if (t == len_b && tid == 0) {                                               \
      float se = 0.f;                                                           \
      for (int j = 0; j < 64; j++) se += __bfloat162float(e_b[BUF][j]);         \
      out[b] = (m + lg2(se)) * LN2F;                                            \
    }                                                                           \
    m_prev = m;                                                                 \
    m = sb + em0_prev + em0n;                                                   \
    em0_prev = em0n;                                                            \
    emr0 = emr1; emr1 = emr2; emr2 = emNew;                                     \
  }

  for (int tb = 0; tb < N_; tb += 2) {
    STEP(0)
    STEP(1)
  }
#undef STEP
}

// ---------------------------------------------------------------------------
extern "C" void kernel_launch(void* const* d_in, const int* in_sizes, int n_in,
                              void* d_out, int out_size) {
  const float* feat    = (const float*)d_in[0];
  const int*   lengths = (const int*)d_in[1];
  const float* means   = (const float*)d_in[2];
  const float* cov     = (const float*)d_in[3];
  const float* tl      = (const float*)d_in[4];
  const float* il      = (const float*)d_in[5];
  const float* plr     = (const float*)d_in[6];
  float* out = (float*)d_out;

  prep_kernel<<<1, 256>>>(means, cov, tl, il, plr);
  transpose_kernel<<<dim3(16, 2), 256>>>(means, cov);
  emission_kernel<<<(B_ * N_) / 128, 256>>>(feat);
  scan_kernel<<<B_, 128>>>(lengths, out);
}